// round 13
// baseline (speedup 1.0000x reference)
#include <cuda_runtime.h>
#include <cuda_bf16.h>
#include <stdint.h>

#define BATCH      32
#define SEQ_T      512
#define DIM        512
#define MAX_FRAMES 4096
#define F4_ROW     (DIM / 4)                       // 128 float4 per row
#define FPB        32                              // frames per block
#define BLK        256
#define GK         16                              // float4 chains per thread
#define GRID       (BATCH * MAX_FRAMES / FPB)      // 4096

// ---------------------------------------------------------------------------
// R12 structure, MLP probe: BLK=256 x GK=16 chains/thread (16 independent
// LDG.128 then 16 STG.128 per thread). Trades occupancy for per-warp MLP.
// ---------------------------------------------------------------------------
__global__ void __launch_bounds__(BLK)
lr_fused7(const float4* __restrict__ x,
          const int* __restrict__ durations,
          float4* __restrict__ out,
          float* __restrict__ mel_lens)
{
    __shared__ int     s_ends[SEQ_T];
    __shared__ int     s_wsum[8];
    // transposed row map: rowT[c*16 + k] = row of frame c + 2k  (c=0..1, k=0..15)
    __shared__ __align__(16) int16_t s_rowT[FPB];

    const int bid  = blockIdx.x;
    const int b    = bid >> 7;                 // 128 blocks per batch
    const int f0   = (bid & 127) * FPB;
    const int tid  = threadIdx.x;
    const int lane = tid & 31;
    const int warp = tid >> 5;                 // 0..7

    // ---- inclusive scan of this batch's 512 durations (2/thread) ----
    const int2 d2 = ((const int2*)(durations + b * SEQ_T))[tid];
    const int pairsum = d2.x + d2.y;
    int v = pairsum;
    #pragma unroll
    for (int off = 1; off < 32; off <<= 1) {
        int n = __shfl_up_sync(0xffffffffu, v, off);
        if (lane >= off) v += n;
    }
    if (lane == 31) s_wsum[warp] = v;
    __syncthreads();
    if (warp == 0 && lane < 8) {
        int ws = s_wsum[lane];
        #pragma unroll
        for (int off = 1; off < 8; off <<= 1) {
            int n = __shfl_up_sync(0x000000ffu, ws, off);
            if (lane >= off) ws += n;
        }
        s_wsum[lane] = ws;
    }
    __syncthreads();
    const int ebase = (warp > 0 ? s_wsum[warp - 1] : 0) + v - pairsum;
    s_ends[2 * tid]     = ebase + d2.x;
    s_ends[2 * tid + 1] = ebase + d2.x + d2.y;
    __syncthreads();

    const int total = s_ends[SEQ_T - 1];       // <= 3584 < 4096

    // ---- rows for this block's 32 frames (32 threads search) ----
    if (tid < FPB) {
        const int f   = tid;                   // local frame 0..31
        const int pos = f0 + f;
        int16_t row;
        if (pos >= total) {
            row = (int16_t)(-1);
        } else {
            int idx = 0;
            #pragma unroll
            for (int s = 256; s > 0; s >>= 1)
                if (idx + s <= SEQ_T && s_ends[idx + s - 1] <= pos) idx += s;
            row = (int16_t)min(idx, SEQ_T - 1);
        }
        // transposed slot: c = f&1, k = f>>1
        s_rowT[(f & 1) * 16 + (f >> 1)] = row;
    }
    if ((bid & 127) == 0 && tid == 0)
        mel_lens[b] = (float)(total > 0 ? total : 1);
    __syncthreads();

    // ---- copy: 16 independent float4 chains per thread ----
    const float4* __restrict__ xb = x + (size_t)b * SEQ_T * F4_ROW;
    float4* __restrict__ ob = out + ((size_t)b * MAX_FRAMES + f0) * F4_ROW;

    // two LDS.128: rows for chains k=0..15 (frame c + 2k)
    const int c = tid >> 7;                    // 0..1
    int16_t rr[GK];
    *(int4*)(rr)     = *(const int4*)&s_rowT[c * 16];
    *(int4*)(rr + 8) = *(const int4*)&s_rowT[c * 16 + 8];

    float4 vv[GK];
    #pragma unroll
    for (int k = 0; k < GK; ++k) {
        const int r = (int)rr[k];
        if (r < 0) {
            vv[k] = make_float4(0.f, 0.f, 0.f, 0.f);
        } else {
            const int g     = tid + k * BLK;
            const int lane4 = g & (F4_ROW - 1);
            vv[k] = __ldg(&xb[r * F4_ROW + lane4]);
        }
    }

    #pragma unroll
    for (int k = 0; k < GK; ++k)
        __stcs(&ob[tid + k * BLK], vv[k]);
}

// ---------------------------------------------------------------------------
extern "C" void kernel_launch(void* const* d_in, const int* in_sizes, int n_in,
                              void* d_out, int out_size)
{
    const float* x         = (const float*)d_in[0];   // (32, 512, 512) f32
    const int*   durations = (const int*)d_in[1];     // (32, 512) i32
    float* out = (float*)d_out;
    float* mel_lens = out + (size_t)BATCH * MAX_FRAMES * DIM;

    lr_fused7<<<GRID, BLK>>>((const float4*)x, durations,
                             (float4*)out, mel_lens);
}

// round 14
// speedup vs baseline: 1.0351x; 1.0351x over previous
#include <cuda_runtime.h>
#include <cuda_bf16.h>
#include <stdint.h>

#define BATCH      32
#define SEQ_T      512
#define DIM        512
#define MAX_FRAMES 4096
#define F4_ROW     (DIM / 4)                       // 128 float4 per row
#define FPB        32                              // frames per block
#define BLK        512
#define GK         8                               // float4 chains per thread
#define GRID       (BATCH * MAX_FRAMES / FPB)      // 4096

// ---------------------------------------------------------------------------
// Final kernel (champion shape, measured 45.5us twice):
//   - one fused launch, self-sufficient blocks (no inter-block sync)
//   - per-block warp-shuffle scan of its batch's 512 durations (L2-hot)
//   - 32 threads binary-search their frame's source row; rows stored
//     transposed so each thread picks up its 8 chain-rows with one LDS.128
//   - copy: 8 independent float4 chains per thread, __ldg reads,
//     __stcs streaming stores (write stream drains with the kernel;
//     .wb variant regressed by +8us wall via post-kernel L2 drain)
// ---------------------------------------------------------------------------
__global__ void __launch_bounds__(BLK)
lr_final(const float4* __restrict__ x,
         const int* __restrict__ durations,
         float4* __restrict__ out,
         float* __restrict__ mel_lens)
{
    __shared__ int     s_ends[SEQ_T];
    __shared__ int     s_wsum[16];
    // transposed row map: rowT[c*8 + k] = row of frame c + 4k  (c=0..3, k=0..7)
    __shared__ __align__(16) int16_t s_rowT[FPB];

    const int bid  = blockIdx.x;
    const int b    = bid >> 7;                 // 128 blocks per batch
    const int f0   = (bid & 127) * FPB;
    const int tid  = threadIdx.x;
    const int lane = tid & 31;
    const int warp = tid >> 5;                 // 0..15

    // ---- inclusive scan of this batch's 512 durations (1/thread) ----
    const int d = durations[b * SEQ_T + tid];
    int v = d;
    #pragma unroll
    for (int off = 1; off < 32; off <<= 1) {
        int n = __shfl_up_sync(0xffffffffu, v, off);
        if (lane >= off) v += n;
    }
    if (lane == 31) s_wsum[warp] = v;
    __syncthreads();
    if (warp == 0 && lane < 16) {
        int ws = s_wsum[lane];
        #pragma unroll
        for (int off = 1; off < 16; off <<= 1) {
            int n = __shfl_up_sync(0x0000ffffu, ws, off);
            if (lane >= off) ws += n;
        }
        s_wsum[lane] = ws;
    }
    __syncthreads();
    s_ends[tid] = (warp > 0 ? s_wsum[warp - 1] : 0) + v;
    __syncthreads();

    const int total = s_ends[SEQ_T - 1];       // <= 3584 < 4096

    // ---- rows for this block's 32 frames (32 threads search) ----
    if (tid < FPB) {
        const int f   = tid;                   // local frame 0..31
        const int pos = f0 + f;
        int16_t row;
        if (pos >= total) {
            row = (int16_t)(-1);
        } else {
            int idx = 0;
            #pragma unroll
            for (int s = 256; s > 0; s >>= 1)
                if (idx + s <= SEQ_T && s_ends[idx + s - 1] <= pos) idx += s;
            row = (int16_t)min(idx, SEQ_T - 1);
        }
        // transposed slot: c = f&3, k = f>>2
        s_rowT[(f & 3) * 8 + (f >> 2)] = row;
    }
    if ((bid & 127) == 0 && tid == 0)
        mel_lens[b] = (float)(total > 0 ? total : 1);
    __syncthreads();

    // ---- copy: 8 independent float4 chains per thread ----
    const float4* __restrict__ xb = x + (size_t)b * SEQ_T * F4_ROW;
    float4* __restrict__ ob = out + ((size_t)b * MAX_FRAMES + f0) * F4_ROW;

    // one LDS.128: rows for chains k=0..7 of this thread (frame c + 4k)
    const int c = tid >> 7;                    // 0..3
    int16_t rr[8];
    *(int4*)rr = *(const int4*)&s_rowT[c * 8];

    float4 vv[GK];
    #pragma unroll
    for (int k = 0; k < GK; ++k) {
        const int r = (int)rr[k];
        if (r < 0) {
            vv[k] = make_float4(0.f, 0.f, 0.f, 0.f);
        } else {
            const int g     = tid + k * BLK;
            const int lane4 = g & (F4_ROW - 1);
            vv[k] = __ldg(&xb[r * F4_ROW + lane4]);
        }
    }

    #pragma unroll
    for (int k = 0; k < GK; ++k)
        __stcs(&ob[tid + k * BLK], vv[k]);
}

// ---------------------------------------------------------------------------
extern "C" void kernel_launch(void* const* d_in, const int* in_sizes, int n_in,
                              void* d_out, int out_size)
{
    const float* x         = (const float*)d_in[0];   // (32, 512, 512) f32
    const int*   durations = (const int*)d_in[1];     // (32, 512) i32
    float* out = (float*)d_out;
    float* mel_lens = out + (size_t)BATCH * MAX_FRAMES * DIM;

    lr_final<<<GRID, BLK>>>((const float4*)x, durations,
                            (float4*)out, mel_lens);
}